// round 2
// baseline (speedup 1.0000x reference)
#include <cuda_runtime.h>
#include <cuda_bf16.h>
#include <math.h>

// Problem: inp [B=16, S=4096, D=512] f32, lengths [16] i32
// out [B, S, D+1=513] f32 : out[b,s,0:512] = inp[b,s,:]
//                           out[b,s,512]   = (s < len[b]) ? cos(s/max(len,1)*pi) : 0
//
// Pure bandwidth problem (~269 MB). One 128-thread CTA per row; float4 loads,
// scalar coalesced stores (row base only 4B-aligned due to 513-stride).

#define B_DIM 16
#define S_DIM 4096
#define D_DIM 512
#define PI_F 3.14159265358979323846f

__global__ __launch_bounds__(128) void concat_pe_kernel(
    const float* __restrict__ inp,
    const int* __restrict__ lengths,
    float* __restrict__ out)
{
    const int row = blockIdx.x;               // 0 .. B*S-1
    const int tid = threadIdx.x;              // 0 .. 127
    const int s = row & (S_DIM - 1);
    const int b = row >> 12;                  // row / 4096

    // Vector load: 128 threads x float4 = 512 floats, perfectly aligned.
    const float4* src = reinterpret_cast<const float4*>(inp + (size_t)row * D_DIM);
    float4 v = src[tid];

    // Output row base: (size_t)row * 513 — only 4B aligned, use scalar stores.
    float* dst = out + (size_t)row * (D_DIM + 1);
    const int c = tid * 4;
    dst[c + 0] = v.x;
    dst[c + 1] = v.y;
    dst[c + 2] = v.z;
    dst[c + 3] = v.w;

    if (tid == 0) {
        const int len = lengths[b];
        float pe = 0.0f;
        if (s < len) {
            float fl = fmaxf((float)len, 1.0f);
            pe = cosf((float)s / fl * PI_F);
        }
        dst[D_DIM] = pe;
    }
}

extern "C" void kernel_launch(void* const* d_in, const int* in_sizes, int n_in,
                              void* d_out, int out_size) {
    const float* inp = (const float*)d_in[0];
    const int* lengths = (const int*)d_in[1];
    float* out = (float*)d_out;

    dim3 grid(B_DIM * S_DIM);  // 65536 rows
    dim3 block(128);
    concat_pe_kernel<<<grid, block>>>(inp, lengths, out);
}